// round 6
// baseline (speedup 1.0000x reference)
#include <cuda_runtime.h>
#include <cstdint>

// ---------------------------------------------------------------------------
// Playlist model:
//   12 embedding towers (3 single-lookup, 9 mean-pooled over L=100)
//   -> concat [B, 12*512] -> Dense(512) relu -> Dense(256) relu -> Dense(128)
//
// Optimization structure:
//   * Small tables (collab=4 rows, dur/apop/afol/tpop=21 rows) are folded
//     through W1 by linearity: P_f = T_f @ W1_f  (88x512 total), so their
//     contribution to layer-1 preactivation is a gather in OUTPUT space.
//     Bucket features additionally use a 21-bin histogram (21 weighted rows
//     instead of 100 gathers).
//   * Big GEMM1 therefore runs with K=3584 (7 features) instead of 6144,
//     with an in-kernel K->W1-row offset map.
// ---------------------------------------------------------------------------

#define NB   1024
#define NL   100
#define KBIG 3584          // 7 * 512

// scratch (device globals; no allocation allowed)
__device__ float g_X [NB * KBIG];   // pooled big-feature embeddings [B, 3584]
__device__ float g_Y0[NB * 512];    // small-feature contribution to layer1 preact
__device__ float g_P [88 * 512];    // precomputed T_small @ W1_slice
__device__ float g_H1[NB * 512];
__device__ float g_H2[NB * 256];

// W1 row offsets for the 7 big features in X-column order:
// name, track_can, artist_name, track_uri, track_name, album, genres
__constant__ int c_WOFF[7] = {0, 1024, 1536, 2048, 2560, 3584, 5632};

// ---------------------------------------------------------------------------
// P[r] = T_small[row] @ W1[off.. off+512]   (88 rows total)
// rows: collab [0,4), dur [4,25), apop [25,46), afol [46,67), tpop [67,88)
// ---------------------------------------------------------------------------
__global__ void precompute_P(const float* __restrict__ T_collab,
                             const float* __restrict__ T_dur,
                             const float* __restrict__ T_apop,
                             const float* __restrict__ T_afol,
                             const float* __restrict__ T_tpop,
                             const float* __restrict__ W1) {
    __shared__ float s_t[512];
    int r = blockIdx.x;
    const float* T; int row; int off;
    if (r < 4)       { T = T_collab; row = r;      off = 512;  }
    else if (r < 25) { T = T_dur;    row = r - 4;  off = 3072; }
    else if (r < 46) { T = T_apop;   row = r - 25; off = 4096; }
    else if (r < 67) { T = T_afol;   row = r - 46; off = 4608; }
    else             { T = T_tpop;   row = r - 67; off = 5120; }
    int n = threadIdx.x;                       // 512 threads
    s_t[n] = T[row * 512 + n];
    __syncthreads();
    float acc = 0.0f;
    const float* w = W1 + (size_t)off * 512 + n;
    #pragma unroll 8
    for (int k = 0; k < 512; ++k)
        acc = fmaf(s_t[k], w[(size_t)k * 512], acc);
    g_P[r * 512 + n] = acc;
}

// ---------------------------------------------------------------------------
// Small-feature contribution: Y0[b] = P_collab[id] + 0.01 * sum_f sum_v cnt*P
// ---------------------------------------------------------------------------
__global__ void small_pool(const int* __restrict__ id_collab,
                           const int* __restrict__ seq_dur,
                           const int* __restrict__ seq_apop,
                           const int* __restrict__ seq_afol,
                           const int* __restrict__ seq_tpop) {
    __shared__ int cnt[21];
    const int b = blockIdx.x, t = threadIdx.x;     // 128 threads, float4 lanes
    const float4* P4 = (const float4*)g_P;

    const int idc = id_collab[b];
    float4 acc = __ldg(&P4[(size_t)idc * 128 + t]);
    float4 ab  = make_float4(0.f, 0.f, 0.f, 0.f);

    const int* seqs[4]  = {seq_dur, seq_apop, seq_afol, seq_tpop};
    const int  pbase[4] = {4, 25, 46, 67};

    for (int j = 0; j < 4; ++j) {
        if (t < 21) cnt[t] = 0;
        __syncthreads();
        if (t < NL) atomicAdd(&cnt[seqs[j][b * NL + t]], 1);
        __syncthreads();
        #pragma unroll
        for (int v = 0; v < 21; ++v) {
            int c = cnt[v];
            if (c) {
                float fc = (float)c;
                float4 p = __ldg(&P4[(size_t)(pbase[j] + v) * 128 + t]);
                ab.x = fmaf(fc, p.x, ab.x);
                ab.y = fmaf(fc, p.y, ab.y);
                ab.z = fmaf(fc, p.z, ab.z);
                ab.w = fmaf(fc, p.w, ab.w);
            }
        }
        __syncthreads();
    }
    float4 o;
    o.x = acc.x + 0.01f * ab.x;
    o.y = acc.y + 0.01f * ab.y;
    o.z = acc.z + 0.01f * ab.z;
    o.w = acc.w + 0.01f * ab.w;
    ((float4*)g_Y0)[(size_t)b * 128 + t] = o;
}

// ---------------------------------------------------------------------------
// Big-feature pooling -> g_X [B, 3584]
// grid (1024, 7); f<2 are single-lookup (name, track_can), f>=2 mean-pool.
// ---------------------------------------------------------------------------
struct BigArgs {
    const float* tbl[7];
    const int*   idx[7];
};

__global__ void __launch_bounds__(128) big_pool(BigArgs a) {
    const int b = blockIdx.x, f = blockIdx.y, t = threadIdx.x;   // 128 threads
    const float4* T = (const float4*)a.tbl[f];
    float4* dst = ((float4*)g_X) + (size_t)b * (KBIG / 4) + f * 128 + t;

    if (f < 2) {
        int id = a.idx[f][b];
        *dst = __ldg(&T[(size_t)id * 128 + t]);
        return;
    }
    __shared__ int s_idx[NL];
    if (t < NL) s_idx[t] = a.idx[f][b * NL + t];
    __syncthreads();

    float4 acc = make_float4(0.f, 0.f, 0.f, 0.f);
    #pragma unroll 4
    for (int l = 0; l < NL; ++l) {
        float4 v = __ldg(&T[(size_t)s_idx[l] * 128 + t]);
        acc.x += v.x; acc.y += v.y; acc.z += v.z; acc.w += v.w;
    }
    acc.x *= 0.01f; acc.y *= 0.01f; acc.z *= 0.01f; acc.w *= 0.01f;
    *dst = acc;
}

// ---------------------------------------------------------------------------
// Tiled fp32 GEMM, 256 threads, register double-buffered K tiles.
// MODE 1: B-row remap via c_WOFF + add C0 + bias + relu   (layer 1)
// MODE 2: bias + relu                                      (layer 2)
// MODE 3: bias                                             (layer 3)
// Requires: K % 16 == 0, M % BM == 0, N % BN == 0, BN == 64.
// ---------------------------------------------------------------------------
template<int BM, int BN, int TM, int TN, int MODE>
__global__ void __launch_bounds__(256) gemm_k(
        const float* __restrict__ A, const float* __restrict__ Bm,
        const float* __restrict__ bias, const float* __restrict__ C0,
        float* __restrict__ C, int M, int N, int K) {
    constexpr int BK = 16;
    constexpr int TX = BN / TN;   // 16
    constexpr int TY = BM / TM;   // 16
    static_assert(TX * TY == 256, "256 threads");
    static_assert(BN == 64, "B-tile loader assumes BN==64");

    __shared__ float As[BK][BM + 4];
    __shared__ float Bs[BK][BN + 4];

    const int tid = threadIdx.x;
    const int tx = tid % TX, ty = tid / TX;
    const int m0 = blockIdx.y * BM, n0 = blockIdx.x * BN;

    // A loader: float4 along K; covers BM rows x 16 k
    const int  a_m   = tid >> 2;
    const int  a_k   = (tid & 3) << 2;
    const bool a_act = (BM * 4 >= 256) ? true : (tid < BM * 4);
    // B loader: float4 along N; 16 k x 64 n
    const int  b_k = tid >> 4;
    const int  b_n = (tid & 15) << 2;

    float4 ra = make_float4(0.f, 0.f, 0.f, 0.f);
    float4 rb;

    if (a_act) ra = *(const float4*)(A + (size_t)(m0 + a_m) * K + a_k);
    {
        int kg = b_k;
        int wr = (MODE == 1) ? (c_WOFF[kg >> 9] + (kg & 511)) : kg;
        rb = *(const float4*)(Bm + (size_t)wr * N + n0 + b_n);
    }

    float acc[TM][TN];
    #pragma unroll
    for (int i = 0; i < TM; ++i)
        #pragma unroll
        for (int j = 0; j < TN; ++j) acc[i][j] = 0.f;

    const int NT = K / BK;
    for (int t = 0; t < NT; ++t) {
        if (a_act) {
            As[a_k + 0][a_m] = ra.x;
            As[a_k + 1][a_m] = ra.y;
            As[a_k + 2][a_m] = ra.z;
            As[a_k + 3][a_m] = ra.w;
        }
        *(float4*)&Bs[b_k][b_n] = rb;
        __syncthreads();

        if (t + 1 < NT) {        // prefetch next tile into registers
            int k0 = (t + 1) * BK;
            if (a_act) ra = *(const float4*)(A + (size_t)(m0 + a_m) * K + k0 + a_k);
            int kg = k0 + b_k;
            int wr = (MODE == 1) ? (c_WOFF[kg >> 9] + (kg & 511)) : kg;
            rb = *(const float4*)(Bm + (size_t)wr * N + n0 + b_n);
        }

        #pragma unroll
        for (int kk = 0; kk < BK; ++kk) {
            float af[TM], bf[TN];
            #pragma unroll
            for (int i = 0; i < TM; ++i) af[i] = As[kk][ty * TM + i];
            #pragma unroll
            for (int j = 0; j < TN; ++j) bf[j] = Bs[kk][tx * TN + j];
            #pragma unroll
            for (int i = 0; i < TM; ++i)
                #pragma unroll
                for (int j = 0; j < TN; ++j)
                    acc[i][j] = fmaf(af[i], bf[j], acc[i][j]);
        }
        __syncthreads();
    }

    #pragma unroll
    for (int i = 0; i < TM; ++i) {
        int row = m0 + ty * TM + i;
        #pragma unroll
        for (int j = 0; j < TN; ++j) {
            int col = n0 + tx * TN + j;
            float v = acc[i][j] + bias[col];
            if (MODE == 1) v += C0[(size_t)row * N + col];
            if (MODE != 3) v = fmaxf(v, 0.0f);
            C[(size_t)row * N + col] = v;
        }
    }
}

// ---------------------------------------------------------------------------
extern "C" void kernel_launch(void* const* d_in, const int* in_sizes, int n_in,
                              void* d_out, int out_size) {
    (void)in_sizes; (void)n_in; (void)out_size;

    const float* T_name        = (const float*)d_in[0];
    const float* T_collab      = (const float*)d_in[1];
    const float* T_track_can   = (const float*)d_in[2];
    const float* T_artist_name = (const float*)d_in[3];
    const float* T_track_uri   = (const float*)d_in[4];
    const float* T_track_name  = (const float*)d_in[5];
    const float* T_dur         = (const float*)d_in[6];
    const float* T_album       = (const float*)d_in[7];
    const float* T_apop        = (const float*)d_in[8];
    const float* T_afol        = (const float*)d_in[9];
    const float* T_tpop        = (const float*)d_in[10];
    const float* T_genres      = (const float*)d_in[11];
    const float* W1 = (const float*)d_in[12];
    const float* b1 = (const float*)d_in[13];
    const float* W2 = (const float*)d_in[14];
    const float* b2 = (const float*)d_in[15];
    const float* W3 = (const float*)d_in[16];
    const float* b3 = (const float*)d_in[17];
    const int* id_name         = (const int*)d_in[18];
    const int* id_collab       = (const int*)d_in[19];
    const int* id_track_can    = (const int*)d_in[20];
    const int* seq_artist_name = (const int*)d_in[21];
    const int* seq_track_uri   = (const int*)d_in[22];
    const int* seq_track_name  = (const int*)d_in[23];
    const int* seq_dur         = (const int*)d_in[24];
    const int* seq_album       = (const int*)d_in[25];
    const int* seq_apop        = (const int*)d_in[26];
    const int* seq_afol        = (const int*)d_in[27];
    const int* seq_tpop        = (const int*)d_in[28];
    const int* seq_genres      = (const int*)d_in[29];

    float *Xp, *Y0, *H1, *H2;
    cudaGetSymbolAddress((void**)&Xp, g_X);
    cudaGetSymbolAddress((void**)&Y0, g_Y0);
    cudaGetSymbolAddress((void**)&H1, g_H1);
    cudaGetSymbolAddress((void**)&H2, g_H2);

    // big-feature gathers (DRAM-bound; longest) + small-feature fold
    BigArgs ba;
    ba.tbl[0] = T_name;        ba.idx[0] = id_name;
    ba.tbl[1] = T_track_can;   ba.idx[1] = id_track_can;
    ba.tbl[2] = T_artist_name; ba.idx[2] = seq_artist_name;
    ba.tbl[3] = T_track_uri;   ba.idx[3] = seq_track_uri;
    ba.tbl[4] = T_track_name;  ba.idx[4] = seq_track_name;
    ba.tbl[5] = T_album;       ba.idx[5] = seq_album;
    ba.tbl[6] = T_genres;      ba.idx[6] = seq_genres;

    big_pool<<<dim3(NB, 7), 128>>>(ba);
    precompute_P<<<88, 512>>>(T_collab, T_dur, T_apop, T_afol, T_tpop, W1);
    small_pool<<<NB, 128>>>(id_collab, seq_dur, seq_apop, seq_afol, seq_tpop);

    // layer 1: [1024,3584] @ W1(remapped rows) + Y0 + b1, relu
    gemm_k<64, 64, 4, 4, 1><<<dim3(512 / 64, NB / 64), 256>>>(
        Xp, W1, b1, Y0, H1, NB, 512, KBIG);
    // layer 2: [1024,512] @ W2 + b2, relu
    gemm_k<32, 64, 2, 4, 2><<<dim3(256 / 64, NB / 32), 256>>>(
        H1, W2, b2, nullptr, H2, NB, 256, 512);
    // layer 3: [1024,256] @ W3 + b3 -> output
    gemm_k<32, 64, 2, 4, 3><<<dim3(128 / 64, NB / 32), 256>>>(
        H2, W3, b3, nullptr, (float*)d_out, NB, 128, 256);
}

// round 7
// speedup vs baseline: 1.0022x; 1.0022x over previous
#include <cuda_runtime.h>
#include <cstdint>

// ---------------------------------------------------------------------------
// Playlist model:
//   12 embedding towers (3 single-lookup, 9 mean-pooled over L=100)
//   -> concat [B, 12*512] -> Dense(512) relu -> Dense(256) relu -> Dense(128)
//
// Optimization structure:
//   * Small tables (collab=4 rows, dur/apop/afol/tpop=21 rows) are folded
//     through W1 by linearity: P_f = T_f @ W1_f  (88x512 total), so their
//     contribution to layer-1 preactivation is a gather in OUTPUT space.
//     Bucket features additionally use a 21-bin histogram (21 weighted rows
//     instead of 100 gathers).
//   * Big GEMM1 therefore runs with K=3584 (7 features) instead of 6144,
//     with an in-kernel K->W1-row offset map.
// ---------------------------------------------------------------------------

#define NB   1024
#define NL   100
#define KBIG 3584          // 7 * 512

// scratch (device globals; no allocation allowed)
__device__ float g_X [NB * KBIG];   // pooled big-feature embeddings [B, 3584]
__device__ float g_Y0[NB * 512];    // small-feature contribution to layer1 preact
__device__ float g_P [88 * 512];    // precomputed T_small @ W1_slice
__device__ float g_H1[NB * 512];
__device__ float g_H2[NB * 256];

// W1 row offsets for the 7 big features in X-column order:
// name, track_can, artist_name, track_uri, track_name, album, genres
__constant__ int c_WOFF[7] = {0, 1024, 1536, 2048, 2560, 3584, 5632};

// ---------------------------------------------------------------------------
// P[r] = T_small[row] @ W1[off.. off+512]   (88 rows total)
// rows: collab [0,4), dur [4,25), apop [25,46), afol [46,67), tpop [67,88)
// ---------------------------------------------------------------------------
__global__ void precompute_P(const float* __restrict__ T_collab,
                             const float* __restrict__ T_dur,
                             const float* __restrict__ T_apop,
                             const float* __restrict__ T_afol,
                             const float* __restrict__ T_tpop,
                             const float* __restrict__ W1) {
    __shared__ float s_t[512];
    int r = blockIdx.x;
    const float* T; int row; int off;
    if (r < 4)       { T = T_collab; row = r;      off = 512;  }
    else if (r < 25) { T = T_dur;    row = r - 4;  off = 3072; }
    else if (r < 46) { T = T_apop;   row = r - 25; off = 4096; }
    else if (r < 67) { T = T_afol;   row = r - 46; off = 4608; }
    else             { T = T_tpop;   row = r - 67; off = 5120; }
    int n = threadIdx.x;                       // 512 threads
    s_t[n] = T[row * 512 + n];
    __syncthreads();
    float acc = 0.0f;
    const float* w = W1 + (size_t)off * 512 + n;
    #pragma unroll 8
    for (int k = 0; k < 512; ++k)
        acc = fmaf(s_t[k], w[(size_t)k * 512], acc);
    g_P[r * 512 + n] = acc;
}

// ---------------------------------------------------------------------------
// Small-feature contribution: Y0[b] = P_collab[id] + 0.01 * sum_f sum_v cnt*P
// ---------------------------------------------------------------------------
__global__ void small_pool(const int* __restrict__ id_collab,
                           const int* __restrict__ seq_dur,
                           const int* __restrict__ seq_apop,
                           const int* __restrict__ seq_afol,
                           const int* __restrict__ seq_tpop) {
    __shared__ int cnt[21];
    const int b = blockIdx.x, t = threadIdx.x;     // 128 threads, float4 lanes
    const float4* P4 = (const float4*)g_P;

    const int idc = id_collab[b];
    float4 acc = __ldg(&P4[(size_t)idc * 128 + t]);
    float4 ab  = make_float4(0.f, 0.f, 0.f, 0.f);

    const int* seqs[4]  = {seq_dur, seq_apop, seq_afol, seq_tpop};
    const int  pbase[4] = {4, 25, 46, 67};

    for (int j = 0; j < 4; ++j) {
        if (t < 21) cnt[t] = 0;
        __syncthreads();
        if (t < NL) atomicAdd(&cnt[seqs[j][b * NL + t]], 1);
        __syncthreads();
        #pragma unroll
        for (int v = 0; v < 21; ++v) {
            int c = cnt[v];
            if (c) {
                float fc = (float)c;
                float4 p = __ldg(&P4[(size_t)(pbase[j] + v) * 128 + t]);
                ab.x = fmaf(fc, p.x, ab.x);
                ab.y = fmaf(fc, p.y, ab.y);
                ab.z = fmaf(fc, p.z, ab.z);
                ab.w = fmaf(fc, p.w, ab.w);
            }
        }
        __syncthreads();
    }
    float4 o;
    o.x = acc.x + 0.01f * ab.x;
    o.y = acc.y + 0.01f * ab.y;
    o.z = acc.z + 0.01f * ab.z;
    o.w = acc.w + 0.01f * ab.w;
    ((float4*)g_Y0)[(size_t)b * 128 + t] = o;
}

// ---------------------------------------------------------------------------
// Big-feature pooling -> g_X [B, 3584]
// grid (1024, 7); f<2 are single-lookup (name, track_can), f>=2 mean-pool.
// ---------------------------------------------------------------------------
struct BigArgs {
    const float* tbl[7];
    const int*   idx[7];
};

__global__ void __launch_bounds__(128) big_pool(BigArgs a) {
    const int b = blockIdx.x, f = blockIdx.y, t = threadIdx.x;   // 128 threads
    const float4* T = (const float4*)a.tbl[f];
    float4* dst = ((float4*)g_X) + (size_t)b * (KBIG / 4) + f * 128 + t;

    if (f < 2) {
        int id = a.idx[f][b];
        *dst = __ldg(&T[(size_t)id * 128 + t]);
        return;
    }
    __shared__ int s_idx[NL];
    if (t < NL) s_idx[t] = a.idx[f][b * NL + t];
    __syncthreads();

    float4 acc = make_float4(0.f, 0.f, 0.f, 0.f);
    #pragma unroll 4
    for (int l = 0; l < NL; ++l) {
        float4 v = __ldg(&T[(size_t)s_idx[l] * 128 + t]);
        acc.x += v.x; acc.y += v.y; acc.z += v.z; acc.w += v.w;
    }
    acc.x *= 0.01f; acc.y *= 0.01f; acc.z *= 0.01f; acc.w *= 0.01f;
    *dst = acc;
}

// ---------------------------------------------------------------------------
// Tiled fp32 GEMM, 256 threads, register double-buffered K tiles.
// MODE 1: B-row remap via c_WOFF + add C0 + bias + relu   (layer 1)
// MODE 2: bias + relu                                      (layer 2)
// MODE 3: bias                                             (layer 3)
// Requires: K % 16 == 0, M % BM == 0, N % BN == 0, BN == 64.
// ---------------------------------------------------------------------------
template<int BM, int BN, int TM, int TN, int MODE>
__global__ void __launch_bounds__(256) gemm_k(
        const float* __restrict__ A, const float* __restrict__ Bm,
        const float* __restrict__ bias, const float* __restrict__ C0,
        float* __restrict__ C, int M, int N, int K) {
    constexpr int BK = 16;
    constexpr int TX = BN / TN;   // 16
    constexpr int TY = BM / TM;   // 16
    static_assert(TX * TY == 256, "256 threads");
    static_assert(BN == 64, "B-tile loader assumes BN==64");

    __shared__ float As[BK][BM + 4];
    __shared__ float Bs[BK][BN + 4];

    const int tid = threadIdx.x;
    const int tx = tid % TX, ty = tid / TX;
    const int m0 = blockIdx.y * BM, n0 = blockIdx.x * BN;

    // A loader: float4 along K; covers BM rows x 16 k
    const int  a_m   = tid >> 2;
    const int  a_k   = (tid & 3) << 2;
    const bool a_act = (BM * 4 >= 256) ? true : (tid < BM * 4);
    // B loader: float4 along N; 16 k x 64 n
    const int  b_k = tid >> 4;
    const int  b_n = (tid & 15) << 2;

    float4 ra = make_float4(0.f, 0.f, 0.f, 0.f);
    float4 rb;

    if (a_act) ra = *(const float4*)(A + (size_t)(m0 + a_m) * K + a_k);
    {
        int kg = b_k;
        int wr = (MODE == 1) ? (c_WOFF[kg >> 9] + (kg & 511)) : kg;
        rb = *(const float4*)(Bm + (size_t)wr * N + n0 + b_n);
    }

    float acc[TM][TN];
    #pragma unroll
    for (int i = 0; i < TM; ++i)
        #pragma unroll
        for (int j = 0; j < TN; ++j) acc[i][j] = 0.f;

    const int NT = K / BK;
    for (int t = 0; t < NT; ++t) {
        if (a_act) {
            As[a_k + 0][a_m] = ra.x;
            As[a_k + 1][a_m] = ra.y;
            As[a_k + 2][a_m] = ra.z;
            As[a_k + 3][a_m] = ra.w;
        }
        *(float4*)&Bs[b_k][b_n] = rb;
        __syncthreads();

        if (t + 1 < NT) {        // prefetch next tile into registers
            int k0 = (t + 1) * BK;
            if (a_act) ra = *(const float4*)(A + (size_t)(m0 + a_m) * K + k0 + a_k);
            int kg = k0 + b_k;
            int wr = (MODE == 1) ? (c_WOFF[kg >> 9] + (kg & 511)) : kg;
            rb = *(const float4*)(Bm + (size_t)wr * N + n0 + b_n);
        }

        #pragma unroll
        for (int kk = 0; kk < BK; ++kk) {
            float af[TM], bf[TN];
            #pragma unroll
            for (int i = 0; i < TM; ++i) af[i] = As[kk][ty * TM + i];
            #pragma unroll
            for (int j = 0; j < TN; ++j) bf[j] = Bs[kk][tx * TN + j];
            #pragma unroll
            for (int i = 0; i < TM; ++i)
                #pragma unroll
                for (int j = 0; j < TN; ++j)
                    acc[i][j] = fmaf(af[i], bf[j], acc[i][j]);
        }
        __syncthreads();
    }

    #pragma unroll
    for (int i = 0; i < TM; ++i) {
        int row = m0 + ty * TM + i;
        #pragma unroll
        for (int j = 0; j < TN; ++j) {
            int col = n0 + tx * TN + j;
            float v = acc[i][j] + bias[col];
            if (MODE == 1) v += C0[(size_t)row * N + col];
            if (MODE != 3) v = fmaxf(v, 0.0f);
            C[(size_t)row * N + col] = v;
        }
    }
}

// ---------------------------------------------------------------------------
extern "C" void kernel_launch(void* const* d_in, const int* in_sizes, int n_in,
                              void* d_out, int out_size) {
    (void)in_sizes; (void)n_in; (void)out_size;

    const float* T_name        = (const float*)d_in[0];
    const float* T_collab      = (const float*)d_in[1];
    const float* T_track_can   = (const float*)d_in[2];
    const float* T_artist_name = (const float*)d_in[3];
    const float* T_track_uri   = (const float*)d_in[4];
    const float* T_track_name  = (const float*)d_in[5];
    const float* T_dur         = (const float*)d_in[6];
    const float* T_album       = (const float*)d_in[7];
    const float* T_apop        = (const float*)d_in[8];
    const float* T_afol        = (const float*)d_in[9];
    const float* T_tpop        = (const float*)d_in[10];
    const float* T_genres      = (const float*)d_in[11];
    const float* W1 = (const float*)d_in[12];
    const float* b1 = (const float*)d_in[13];
    const float* W2 = (const float*)d_in[14];
    const float* b2 = (const float*)d_in[15];
    const float* W3 = (const float*)d_in[16];
    const float* b3 = (const float*)d_in[17];
    const int* id_name         = (const int*)d_in[18];
    const int* id_collab       = (const int*)d_in[19];
    const int* id_track_can    = (const int*)d_in[20];
    const int* seq_artist_name = (const int*)d_in[21];
    const int* seq_track_uri   = (const int*)d_in[22];
    const int* seq_track_name  = (const int*)d_in[23];
    const int* seq_dur         = (const int*)d_in[24];
    const int* seq_album       = (const int*)d_in[25];
    const int* seq_apop        = (const int*)d_in[26];
    const int* seq_afol        = (const int*)d_in[27];
    const int* seq_tpop        = (const int*)d_in[28];
    const int* seq_genres      = (const int*)d_in[29];

    float *Xp, *Y0, *H1, *H2;
    cudaGetSymbolAddress((void**)&Xp, g_X);
    cudaGetSymbolAddress((void**)&Y0, g_Y0);
    cudaGetSymbolAddress((void**)&H1, g_H1);
    cudaGetSymbolAddress((void**)&H2, g_H2);

    // big-feature gathers (DRAM-bound; longest) + small-feature fold
    BigArgs ba;
    ba.tbl[0] = T_name;        ba.idx[0] = id_name;
    ba.tbl[1] = T_track_can;   ba.idx[1] = id_track_can;
    ba.tbl[2] = T_artist_name; ba.idx[2] = seq_artist_name;
    ba.tbl[3] = T_track_uri;   ba.idx[3] = seq_track_uri;
    ba.tbl[4] = T_track_name;  ba.idx[4] = seq_track_name;
    ba.tbl[5] = T_album;       ba.idx[5] = seq_album;
    ba.tbl[6] = T_genres;      ba.idx[6] = seq_genres;

    big_pool<<<dim3(NB, 7), 128>>>(ba);
    precompute_P<<<88, 512>>>(T_collab, T_dur, T_apop, T_afol, T_tpop, W1);
    small_pool<<<NB, 128>>>(id_collab, seq_dur, seq_apop, seq_afol, seq_tpop);

    // layer 1: [1024,3584] @ W1(remapped rows) + Y0 + b1, relu
    gemm_k<64, 64, 4, 4, 1><<<dim3(512 / 64, NB / 64), 256>>>(
        Xp, W1, b1, Y0, H1, NB, 512, KBIG);
    // layer 2: [1024,512] @ W2 + b2, relu
    gemm_k<32, 64, 2, 4, 2><<<dim3(256 / 64, NB / 32), 256>>>(
        H1, W2, b2, nullptr, H2, NB, 256, 512);
    // layer 3: [1024,256] @ W3 + b3 -> output
    gemm_k<32, 64, 2, 4, 3><<<dim3(128 / 64, NB / 32), 256>>>(
        H2, W3, b3, nullptr, (float*)d_out, NB, 128, 256);
}

// round 8
// speedup vs baseline: 1.3180x; 1.3151x over previous
#include <cuda_runtime.h>
#include <cstdint>

// ---------------------------------------------------------------------------
// Playlist model:
//   12 embedding towers (3 single-lookup, 9 mean-pooled over L=100)
//   -> concat [B, 12*512] -> Dense(512) relu -> Dense(256) relu -> Dense(128)
//
// Structure:
//   * Small tables folded through W1 by linearity (P = T_small @ W1_slice,
//     88x512), bucket features via 21-bin histogram -> Y0 [B,512].
//   * Big GEMM1 runs K=3584 (7 big features) with an in-kernel K->W1 row map.
//   * All GEMMs are split-K across gridDim.z into fp32 partials + a combine
//     kernel (fixed-order sum => deterministic). This lifts grid from
//     128/128/64 blocks to 512/256/256 -> 3-4 blocks/SM, hiding LDS latency
//     and barrier stalls that capped fma util at 20.5% in R7.
// ---------------------------------------------------------------------------

#define NB   1024
#define NL   100
#define KBIG 3584          // 7 * 512

__device__ float g_X   [NB * KBIG];
__device__ float g_Y0  [NB * 512];
__device__ float g_P   [88 * 512];
__device__ float g_H1  [NB * 512];
__device__ float g_H2  [NB * 256];
__device__ float g_part[4 * NB * 512];     // split-K partials (max 4 x 1024 x 512)

// W1 row offsets for the 7 big features in X-column order:
// name, track_can, artist_name, track_uri, track_name, album, genres
__constant__ int c_WOFF[7] = {0, 1024, 1536, 2048, 2560, 3584, 5632};

// ---------------------------------------------------------------------------
__global__ void precompute_P(const float* __restrict__ T_collab,
                             const float* __restrict__ T_dur,
                             const float* __restrict__ T_apop,
                             const float* __restrict__ T_afol,
                             const float* __restrict__ T_tpop,
                             const float* __restrict__ W1) {
    __shared__ float s_t[512];
    int r = blockIdx.x;
    const float* T; int row; int off;
    if (r < 4)       { T = T_collab; row = r;      off = 512;  }
    else if (r < 25) { T = T_dur;    row = r - 4;  off = 3072; }
    else if (r < 46) { T = T_apop;   row = r - 25; off = 4096; }
    else if (r < 67) { T = T_afol;   row = r - 46; off = 4608; }
    else             { T = T_tpop;   row = r - 67; off = 5120; }
    int n = threadIdx.x;                       // 512 threads
    s_t[n] = T[row * 512 + n];
    __syncthreads();
    float acc = 0.0f;
    const float* w = W1 + (size_t)off * 512 + n;
    #pragma unroll 8
    for (int k = 0; k < 512; ++k)
        acc = fmaf(s_t[k], w[(size_t)k * 512], acc);
    g_P[r * 512 + n] = acc;
}

// ---------------------------------------------------------------------------
__global__ void small_pool(const int* __restrict__ id_collab,
                           const int* __restrict__ seq_dur,
                           const int* __restrict__ seq_apop,
                           const int* __restrict__ seq_afol,
                           const int* __restrict__ seq_tpop) {
    __shared__ int cnt[21];
    const int b = blockIdx.x, t = threadIdx.x;     // 128 threads, float4 lanes
    const float4* P4 = (const float4*)g_P;

    const int idc = id_collab[b];
    float4 acc = __ldg(&P4[(size_t)idc * 128 + t]);
    float4 ab  = make_float4(0.f, 0.f, 0.f, 0.f);

    const int* seqs[4]  = {seq_dur, seq_apop, seq_afol, seq_tpop};
    const int  pbase[4] = {4, 25, 46, 67};

    for (int j = 0; j < 4; ++j) {
        if (t < 21) cnt[t] = 0;
        __syncthreads();
        if (t < NL) atomicAdd(&cnt[seqs[j][b * NL + t]], 1);
        __syncthreads();
        #pragma unroll
        for (int v = 0; v < 21; ++v) {
            int c = cnt[v];
            if (c) {
                float fc = (float)c;
                float4 p = __ldg(&P4[(size_t)(pbase[j] + v) * 128 + t]);
                ab.x = fmaf(fc, p.x, ab.x);
                ab.y = fmaf(fc, p.y, ab.y);
                ab.z = fmaf(fc, p.z, ab.z);
                ab.w = fmaf(fc, p.w, ab.w);
            }
        }
        __syncthreads();
    }
    float4 o;
    o.x = acc.x + 0.01f * ab.x;
    o.y = acc.y + 0.01f * ab.y;
    o.z = acc.z + 0.01f * ab.z;
    o.w = acc.w + 0.01f * ab.w;
    ((float4*)g_Y0)[(size_t)b * 128 + t] = o;
}

// ---------------------------------------------------------------------------
struct BigArgs {
    const float* tbl[7];
    const int*   idx[7];
};

__global__ void __launch_bounds__(128) big_pool(BigArgs a) {
    const int b = blockIdx.x, f = blockIdx.y, t = threadIdx.x;   // 128 threads
    const float4* T = (const float4*)a.tbl[f];
    float4* dst = ((float4*)g_X) + (size_t)b * (KBIG / 4) + f * 128 + t;

    if (f < 2) {
        int id = a.idx[f][b];
        *dst = __ldg(&T[(size_t)id * 128 + t]);
        return;
    }
    __shared__ int s_idx[NL];
    if (t < NL) s_idx[t] = a.idx[f][b * NL + t];
    __syncthreads();

    float4 acc = make_float4(0.f, 0.f, 0.f, 0.f);
    #pragma unroll 10
    for (int l = 0; l < NL; ++l) {
        float4 v = __ldg(&T[(size_t)s_idx[l] * 128 + t]);
        acc.x += v.x; acc.y += v.y; acc.z += v.z; acc.w += v.w;
    }
    acc.x *= 0.01f; acc.y *= 0.01f; acc.z *= 0.01f; acc.w *= 0.01f;
    *dst = acc;
}

// ---------------------------------------------------------------------------
// Split-K tiled fp32 GEMM, 256 threads, register double-buffered K tiles.
// gridDim.z = splits; z covers Kc columns of K and writes fp32 partials to
// g_part[z*M*N + ...]. No epilogue here (done in combine_k).
// REMAP: map logical K to W1 rows via c_WOFF (layer-1 feature concat skip).
// Requires: Kc % 16 == 0, M % BM == 0, N % BN == 0, BN == 64.
// ---------------------------------------------------------------------------
template<int BM, int BN, int TM, int TN, bool REMAP>
__global__ void __launch_bounds__(256) gemm_split(
        const float* __restrict__ A, const float* __restrict__ Bm,
        int M, int N, int K, int Kc) {
    constexpr int BK = 16;
    constexpr int TX = BN / TN;
    constexpr int TY = BM / TM;
    static_assert(TX * TY == 256, "256 threads");
    static_assert(BN == 64, "B-tile loader assumes BN==64");

    __shared__ float As[BK][BM + 4];
    __shared__ float Bs[BK][BN + 4];

    const int tid = threadIdx.x;
    const int tx = tid % TX, ty = tid / TX;
    const int m0 = blockIdx.y * BM, n0 = blockIdx.x * BN;
    const int k0 = blockIdx.z * Kc;
    float* C = g_part + (size_t)blockIdx.z * M * N;

    // A loader: float4 along K; covers BM rows x 16 k
    const int  a_m   = tid >> 2;
    const int  a_k   = (tid & 3) << 2;
    const bool a_act = (BM * 4 >= 256) ? true : (tid < BM * 4);
    // B loader: float4 along N; 16 k x 64 n
    const int  b_k = tid >> 4;
    const int  b_n = (tid & 15) << 2;

    float4 ra = make_float4(0.f, 0.f, 0.f, 0.f);
    float4 rb;

    if (a_act) ra = *(const float4*)(A + (size_t)(m0 + a_m) * K + k0 + a_k);
    {
        int kg = k0 + b_k;
        int wr = REMAP ? (c_WOFF[kg >> 9] + (kg & 511)) : kg;
        rb = *(const float4*)(Bm + (size_t)wr * N + n0 + b_n);
    }

    float acc[TM][TN];
    #pragma unroll
    for (int i = 0; i < TM; ++i)
        #pragma unroll
        for (int j = 0; j < TN; ++j) acc[i][j] = 0.f;

    const int NT = Kc / BK;
    for (int t = 0; t < NT; ++t) {
        if (a_act) {
            As[a_k + 0][a_m] = ra.x;
            As[a_k + 1][a_m] = ra.y;
            As[a_k + 2][a_m] = ra.z;
            As[a_k + 3][a_m] = ra.w;
        }
        *(float4*)&Bs[b_k][b_n] = rb;
        __syncthreads();

        if (t + 1 < NT) {        // prefetch next tile into registers
            int kk0 = k0 + (t + 1) * BK;
            if (a_act) ra = *(const float4*)(A + (size_t)(m0 + a_m) * K + kk0 + a_k);
            int kg = kk0 + b_k;
            int wr = REMAP ? (c_WOFF[kg >> 9] + (kg & 511)) : kg;
            rb = *(const float4*)(Bm + (size_t)wr * N + n0 + b_n);
        }

        #pragma unroll
        for (int kk = 0; kk < BK; ++kk) {
            float af[TM], bf[TN];
            #pragma unroll
            for (int i = 0; i < TM; ++i) af[i] = As[kk][ty * TM + i];
            #pragma unroll
            for (int j = 0; j < TN; ++j) bf[j] = Bs[kk][tx * TN + j];
            #pragma unroll
            for (int i = 0; i < TM; ++i)
                #pragma unroll
                for (int j = 0; j < TN; ++j)
                    acc[i][j] = fmaf(af[i], bf[j], acc[i][j]);
        }
        __syncthreads();
    }

    #pragma unroll
    for (int i = 0; i < TM; ++i) {
        int row = m0 + ty * TM + i;
        #pragma unroll
        for (int j = 0; j < TN; ++j)
            C[(size_t)row * N + n0 + tx * TN + j] = acc[i][j];
    }
}

// ---------------------------------------------------------------------------
// out = act(sum_z part[z] + bias [+ C0]); fixed order -> deterministic.
// ---------------------------------------------------------------------------
template<int S, bool RELU, bool ADDC0>
__global__ void combine_k(const float* __restrict__ bias,
                          const float* __restrict__ C0,
                          float* __restrict__ out, int MN4, int N4) {
    int i = blockIdx.x * blockDim.x + threadIdx.x;
    if (i >= MN4) return;
    const float4* p = (const float4*)g_part;
    float4 v = __ldg(&((const float4*)bias)[i % N4]);
    #pragma unroll
    for (int s = 0; s < S; ++s) {
        float4 q = p[(size_t)s * MN4 + i];
        v.x += q.x; v.y += q.y; v.z += q.z; v.w += q.w;
    }
    if (ADDC0) {
        float4 c = ((const float4*)C0)[i];
        v.x += c.x; v.y += c.y; v.z += c.z; v.w += c.w;
    }
    if (RELU) {
        v.x = fmaxf(v.x, 0.f); v.y = fmaxf(v.y, 0.f);
        v.z = fmaxf(v.z, 0.f); v.w = fmaxf(v.w, 0.f);
    }
    ((float4*)out)[i] = v;
}

// ---------------------------------------------------------------------------
extern "C" void kernel_launch(void* const* d_in, const int* in_sizes, int n_in,
                              void* d_out, int out_size) {
    (void)in_sizes; (void)n_in; (void)out_size;

    const float* T_name        = (const float*)d_in[0];
    const float* T_collab      = (const float*)d_in[1];
    const float* T_track_can   = (const float*)d_in[2];
    const float* T_artist_name = (const float*)d_in[3];
    const float* T_track_uri   = (const float*)d_in[4];
    const float* T_track_name  = (const float*)d_in[5];
    const float* T_dur         = (const float*)d_in[6];
    const float* T_album       = (const float*)d_in[7];
    const float* T_apop        = (const float*)d_in[8];
    const float* T_afol        = (const float*)d_in[9];
    const float* T_tpop        = (const float*)d_in[10];
    const float* T_genres      = (const float*)d_in[11];
    const float* W1 = (const float*)d_in[12];
    const float* b1 = (const float*)d_in[13];
    const float* W2 = (const float*)d_in[14];
    const float* b2 = (const float*)d_in[15];
    const float* W3 = (const float*)d_in[16];
    const float* b3 = (const float*)d_in[17];
    const int* id_name         = (const int*)d_in[18];
    const int* id_collab       = (const int*)d_in[19];
    const int* id_track_can    = (const int*)d_in[20];
    const int* seq_artist_name = (const int*)d_in[21];
    const int* seq_track_uri   = (const int*)d_in[22];
    const int* seq_track_name  = (const int*)d_in[23];
    const int* seq_dur         = (const int*)d_in[24];
    const int* seq_album       = (const int*)d_in[25];
    const int* seq_apop        = (const int*)d_in[26];
    const int* seq_afol        = (const int*)d_in[27];
    const int* seq_tpop        = (const int*)d_in[28];
    const int* seq_genres      = (const int*)d_in[29];

    float *Xp, *Y0, *H1, *H2;
    cudaGetSymbolAddress((void**)&Xp, g_X);
    cudaGetSymbolAddress((void**)&Y0, g_Y0);
    cudaGetSymbolAddress((void**)&H1, g_H1);
    cudaGetSymbolAddress((void**)&H2, g_H2);

    BigArgs ba;
    ba.tbl[0] = T_name;        ba.idx[0] = id_name;
    ba.tbl[1] = T_track_can;   ba.idx[1] = id_track_can;
    ba.tbl[2] = T_artist_name; ba.idx[2] = seq_artist_name;
    ba.tbl[3] = T_track_uri;   ba.idx[3] = seq_track_uri;
    ba.tbl[4] = T_track_name;  ba.idx[4] = seq_track_name;
    ba.tbl[5] = T_album;       ba.idx[5] = seq_album;
    ba.tbl[6] = T_genres;      ba.idx[6] = seq_genres;

    big_pool<<<dim3(NB, 7), 128>>>(ba);
    precompute_P<<<88, 512>>>(T_collab, T_dur, T_apop, T_afol, T_tpop, W1);
    small_pool<<<NB, 128>>>(id_collab, seq_dur, seq_apop, seq_afol, seq_tpop);

    // layer 1: [1024,3584] @ W1(remap); split-K=4 (Kc=896) -> 512 blocks
    gemm_split<64, 64, 4, 4, true><<<dim3(512 / 64, NB / 64, 4), 256>>>(
        Xp, W1, NB, 512, KBIG, KBIG / 4);
    combine_k<4, true, true><<<(NB * 512 / 4 + 255) / 256, 256>>>(
        b1, Y0, H1, NB * 512 / 4, 512 / 4);

    // layer 2: [1024,512] @ W2; split-K=2 (Kc=256) -> 256 blocks
    gemm_split<32, 64, 2, 4, false><<<dim3(256 / 64, NB / 32, 2), 256>>>(
        H1, W2, NB, 256, 512, 256);
    combine_k<2, true, false><<<(NB * 256 / 4 + 255) / 256, 256>>>(
        b2, nullptr, H2, NB * 256 / 4, 256 / 4);

    // layer 3: [1024,256] @ W3; split-K=4 (Kc=64) -> 256 blocks
    gemm_split<32, 64, 2, 4, false><<<dim3(128 / 64, NB / 32, 4), 256>>>(
        H2, W3, NB, 128, 256, 64);
    combine_k<4, false, false><<<(NB * 128 / 4 + 255) / 256, 256>>>(
        b3, nullptr, (float*)d_out, NB * 128 / 4, 128 / 4);
}

// round 9
// speedup vs baseline: 1.3556x; 1.0285x over previous
#include <cuda_runtime.h>
#include <cstdint>

// ---------------------------------------------------------------------------
// Playlist model:
//   12 embedding towers (3 single-lookup, 9 mean-pooled over L=100)
//   -> concat [B, 12*512] -> Dense(512) relu -> Dense(256) relu -> Dense(128)
//
// Structure:
//   * Small tables folded through W1 by linearity (P = T_small @ W1_slice,
//     88x512), bucket features via 21-bin histogram -> Y0 [B,512].
//   * Big GEMM1 runs K=3584 (7 big features) with an in-kernel K->W1 row map.
//   * All GEMMs are split-K across gridDim.z into fp32 partials + a combine
//     kernel (fixed-order sum => deterministic). This lifts grid from
//     128/128/64 blocks to 512/256/256 -> 3-4 blocks/SM, hiding LDS latency
//     and barrier stalls that capped fma util at 20.5% in R7.
// ---------------------------------------------------------------------------

#define NB   1024
#define NL   100
#define KBIG 3584          // 7 * 512

__device__ float g_X   [NB * KBIG];
__device__ float g_Y0  [NB * 512];
__device__ float g_P   [88 * 512];
__device__ float g_H1  [NB * 512];
__device__ float g_H2  [NB * 256];
__device__ float g_part[4 * NB * 512];     // split-K partials (max 4 x 1024 x 512)

// W1 row offsets for the 7 big features in X-column order:
// name, track_can, artist_name, track_uri, track_name, album, genres
__constant__ int c_WOFF[7] = {0, 1024, 1536, 2048, 2560, 3584, 5632};

// ---------------------------------------------------------------------------
__global__ void precompute_P(const float* __restrict__ T_collab,
                             const float* __restrict__ T_dur,
                             const float* __restrict__ T_apop,
                             const float* __restrict__ T_afol,
                             const float* __restrict__ T_tpop,
                             const float* __restrict__ W1) {
    __shared__ float s_t[512];
    int r = blockIdx.x;
    const float* T; int row; int off;
    if (r < 4)       { T = T_collab; row = r;      off = 512;  }
    else if (r < 25) { T = T_dur;    row = r - 4;  off = 3072; }
    else if (r < 46) { T = T_apop;   row = r - 25; off = 4096; }
    else if (r < 67) { T = T_afol;   row = r - 46; off = 4608; }
    else             { T = T_tpop;   row = r - 67; off = 5120; }
    int n = threadIdx.x;                       // 512 threads
    s_t[n] = T[row * 512 + n];
    __syncthreads();
    float acc = 0.0f;
    const float* w = W1 + (size_t)off * 512 + n;
    #pragma unroll 8
    for (int k = 0; k < 512; ++k)
        acc = fmaf(s_t[k], w[(size_t)k * 512], acc);
    g_P[r * 512 + n] = acc;
}

// ---------------------------------------------------------------------------
__global__ void small_pool(const int* __restrict__ id_collab,
                           const int* __restrict__ seq_dur,
                           const int* __restrict__ seq_apop,
                           const int* __restrict__ seq_afol,
                           const int* __restrict__ seq_tpop) {
    __shared__ int cnt[21];
    const int b = blockIdx.x, t = threadIdx.x;     // 128 threads, float4 lanes
    const float4* P4 = (const float4*)g_P;

    const int idc = id_collab[b];
    float4 acc = __ldg(&P4[(size_t)idc * 128 + t]);
    float4 ab  = make_float4(0.f, 0.f, 0.f, 0.f);

    const int* seqs[4]  = {seq_dur, seq_apop, seq_afol, seq_tpop};
    const int  pbase[4] = {4, 25, 46, 67};

    for (int j = 0; j < 4; ++j) {
        if (t < 21) cnt[t] = 0;
        __syncthreads();
        if (t < NL) atomicAdd(&cnt[seqs[j][b * NL + t]], 1);
        __syncthreads();
        #pragma unroll
        for (int v = 0; v < 21; ++v) {
            int c = cnt[v];
            if (c) {
                float fc = (float)c;
                float4 p = __ldg(&P4[(size_t)(pbase[j] + v) * 128 + t]);
                ab.x = fmaf(fc, p.x, ab.x);
                ab.y = fmaf(fc, p.y, ab.y);
                ab.z = fmaf(fc, p.z, ab.z);
                ab.w = fmaf(fc, p.w, ab.w);
            }
        }
        __syncthreads();
    }
    float4 o;
    o.x = acc.x + 0.01f * ab.x;
    o.y = acc.y + 0.01f * ab.y;
    o.z = acc.z + 0.01f * ab.z;
    o.w = acc.w + 0.01f * ab.w;
    ((float4*)g_Y0)[(size_t)b * 128 + t] = o;
}

// ---------------------------------------------------------------------------
struct BigArgs {
    const float* tbl[7];
    const int*   idx[7];
};

__global__ void __launch_bounds__(128) big_pool(BigArgs a) {
    const int b = blockIdx.x, f = blockIdx.y, t = threadIdx.x;   // 128 threads
    const float4* T = (const float4*)a.tbl[f];
    float4* dst = ((float4*)g_X) + (size_t)b * (KBIG / 4) + f * 128 + t;

    if (f < 2) {
        int id = a.idx[f][b];
        *dst = __ldg(&T[(size_t)id * 128 + t]);
        return;
    }
    __shared__ int s_idx[NL];
    if (t < NL) s_idx[t] = a.idx[f][b * NL + t];
    __syncthreads();

    float4 acc = make_float4(0.f, 0.f, 0.f, 0.f);
    #pragma unroll 10
    for (int l = 0; l < NL; ++l) {
        float4 v = __ldg(&T[(size_t)s_idx[l] * 128 + t]);
        acc.x += v.x; acc.y += v.y; acc.z += v.z; acc.w += v.w;
    }
    acc.x *= 0.01f; acc.y *= 0.01f; acc.z *= 0.01f; acc.w *= 0.01f;
    *dst = acc;
}

// ---------------------------------------------------------------------------
// Split-K tiled fp32 GEMM, 256 threads, register double-buffered K tiles.
// gridDim.z = splits; z covers Kc columns of K and writes fp32 partials to
// g_part[z*M*N + ...]. No epilogue here (done in combine_k).
// REMAP: map logical K to W1 rows via c_WOFF (layer-1 feature concat skip).
// Requires: Kc % 16 == 0, M % BM == 0, N % BN == 0, BN == 64.
// ---------------------------------------------------------------------------
template<int BM, int BN, int TM, int TN, bool REMAP>
__global__ void __launch_bounds__(256) gemm_split(
        const float* __restrict__ A, const float* __restrict__ Bm,
        int M, int N, int K, int Kc) {
    constexpr int BK = 16;
    constexpr int TX = BN / TN;
    constexpr int TY = BM / TM;
    static_assert(TX * TY == 256, "256 threads");
    static_assert(BN == 64, "B-tile loader assumes BN==64");

    __shared__ float As[BK][BM + 4];
    __shared__ float Bs[BK][BN + 4];

    const int tid = threadIdx.x;
    const int tx = tid % TX, ty = tid / TX;
    const int m0 = blockIdx.y * BM, n0 = blockIdx.x * BN;
    const int k0 = blockIdx.z * Kc;
    float* C = g_part + (size_t)blockIdx.z * M * N;

    // A loader: float4 along K; covers BM rows x 16 k
    const int  a_m   = tid >> 2;
    const int  a_k   = (tid & 3) << 2;
    const bool a_act = (BM * 4 >= 256) ? true : (tid < BM * 4);
    // B loader: float4 along N; 16 k x 64 n
    const int  b_k = tid >> 4;
    const int  b_n = (tid & 15) << 2;

    float4 ra = make_float4(0.f, 0.f, 0.f, 0.f);
    float4 rb;

    if (a_act) ra = *(const float4*)(A + (size_t)(m0 + a_m) * K + k0 + a_k);
    {
        int kg = k0 + b_k;
        int wr = REMAP ? (c_WOFF[kg >> 9] + (kg & 511)) : kg;
        rb = *(const float4*)(Bm + (size_t)wr * N + n0 + b_n);
    }

    float acc[TM][TN];
    #pragma unroll
    for (int i = 0; i < TM; ++i)
        #pragma unroll
        for (int j = 0; j < TN; ++j) acc[i][j] = 0.f;

    const int NT = Kc / BK;
    for (int t = 0; t < NT; ++t) {
        if (a_act) {
            As[a_k + 0][a_m] = ra.x;
            As[a_k + 1][a_m] = ra.y;
            As[a_k + 2][a_m] = ra.z;
            As[a_k + 3][a_m] = ra.w;
        }
        *(float4*)&Bs[b_k][b_n] = rb;
        __syncthreads();

        if (t + 1 < NT) {        // prefetch next tile into registers
            int kk0 = k0 + (t + 1) * BK;
            if (a_act) ra = *(const float4*)(A + (size_t)(m0 + a_m) * K + kk0 + a_k);
            int kg = kk0 + b_k;
            int wr = REMAP ? (c_WOFF[kg >> 9] + (kg & 511)) : kg;
            rb = *(const float4*)(Bm + (size_t)wr * N + n0 + b_n);
        }

        #pragma unroll
        for (int kk = 0; kk < BK; ++kk) {
            float af[TM], bf[TN];
            #pragma unroll
            for (int i = 0; i < TM; ++i) af[i] = As[kk][ty * TM + i];
            #pragma unroll
            for (int j = 0; j < TN; ++j) bf[j] = Bs[kk][tx * TN + j];
            #pragma unroll
            for (int i = 0; i < TM; ++i)
                #pragma unroll
                for (int j = 0; j < TN; ++j)
                    acc[i][j] = fmaf(af[i], bf[j], acc[i][j]);
        }
        __syncthreads();
    }

    #pragma unroll
    for (int i = 0; i < TM; ++i) {
        int row = m0 + ty * TM + i;
        #pragma unroll
        for (int j = 0; j < TN; ++j)
            C[(size_t)row * N + n0 + tx * TN + j] = acc[i][j];
    }
}

// ---------------------------------------------------------------------------
// out = act(sum_z part[z] + bias [+ C0]); fixed order -> deterministic.
// ---------------------------------------------------------------------------
template<int S, bool RELU, bool ADDC0>
__global__ void combine_k(const float* __restrict__ bias,
                          const float* __restrict__ C0,
                          float* __restrict__ out, int MN4, int N4) {
    int i = blockIdx.x * blockDim.x + threadIdx.x;
    if (i >= MN4) return;
    const float4* p = (const float4*)g_part;
    float4 v = __ldg(&((const float4*)bias)[i % N4]);
    #pragma unroll
    for (int s = 0; s < S; ++s) {
        float4 q = p[(size_t)s * MN4 + i];
        v.x += q.x; v.y += q.y; v.z += q.z; v.w += q.w;
    }
    if (ADDC0) {
        float4 c = ((const float4*)C0)[i];
        v.x += c.x; v.y += c.y; v.z += c.z; v.w += c.w;
    }
    if (RELU) {
        v.x = fmaxf(v.x, 0.f); v.y = fmaxf(v.y, 0.f);
        v.z = fmaxf(v.z, 0.f); v.w = fmaxf(v.w, 0.f);
    }
    ((float4*)out)[i] = v;
}

// ---------------------------------------------------------------------------
extern "C" void kernel_launch(void* const* d_in, const int* in_sizes, int n_in,
                              void* d_out, int out_size) {
    (void)in_sizes; (void)n_in; (void)out_size;

    const float* T_name        = (const float*)d_in[0];
    const float* T_collab      = (const float*)d_in[1];
    const float* T_track_can   = (const float*)d_in[2];
    const float* T_artist_name = (const float*)d_in[3];
    const float* T_track_uri   = (const float*)d_in[4];
    const float* T_track_name  = (const float*)d_in[5];
    const float* T_dur         = (const float*)d_in[6];
    const float* T_album       = (const float*)d_in[7];
    const float* T_apop        = (const float*)d_in[8];
    const float* T_afol        = (const float*)d_in[9];
    const float* T_tpop        = (const float*)d_in[10];
    const float* T_genres      = (const float*)d_in[11];
    const float* W1 = (const float*)d_in[12];
    const float* b1 = (const float*)d_in[13];
    const float* W2 = (const float*)d_in[14];
    const float* b2 = (const float*)d_in[15];
    const float* W3 = (const float*)d_in[16];
    const float* b3 = (const float*)d_in[17];
    const int* id_name         = (const int*)d_in[18];
    const int* id_collab       = (const int*)d_in[19];
    const int* id_track_can    = (const int*)d_in[20];
    const int* seq_artist_name = (const int*)d_in[21];
    const int* seq_track_uri   = (const int*)d_in[22];
    const int* seq_track_name  = (const int*)d_in[23];
    const int* seq_dur         = (const int*)d_in[24];
    const int* seq_album       = (const int*)d_in[25];
    const int* seq_apop        = (const int*)d_in[26];
    const int* seq_afol        = (const int*)d_in[27];
    const int* seq_tpop        = (const int*)d_in[28];
    const int* seq_genres      = (const int*)d_in[29];

    float *Xp, *Y0, *H1, *H2;
    cudaGetSymbolAddress((void**)&Xp, g_X);
    cudaGetSymbolAddress((void**)&Y0, g_Y0);
    cudaGetSymbolAddress((void**)&H1, g_H1);
    cudaGetSymbolAddress((void**)&H2, g_H2);

    BigArgs ba;
    ba.tbl[0] = T_name;        ba.idx[0] = id_name;
    ba.tbl[1] = T_track_can;   ba.idx[1] = id_track_can;
    ba.tbl[2] = T_artist_name; ba.idx[2] = seq_artist_name;
    ba.tbl[3] = T_track_uri;   ba.idx[3] = seq_track_uri;
    ba.tbl[4] = T_track_name;  ba.idx[4] = seq_track_name;
    ba.tbl[5] = T_album;       ba.idx[5] = seq_album;
    ba.tbl[6] = T_genres;      ba.idx[6] = seq_genres;

    big_pool<<<dim3(NB, 7), 128>>>(ba);
    precompute_P<<<88, 512>>>(T_collab, T_dur, T_apop, T_afol, T_tpop, W1);
    small_pool<<<NB, 128>>>(id_collab, seq_dur, seq_apop, seq_afol, seq_tpop);

    // layer 1: [1024,3584] @ W1(remap); split-K=4 (Kc=896) -> 512 blocks
    gemm_split<64, 64, 4, 4, true><<<dim3(512 / 64, NB / 64, 4), 256>>>(
        Xp, W1, NB, 512, KBIG, KBIG / 4);
    combine_k<4, true, true><<<(NB * 512 / 4 + 255) / 256, 256>>>(
        b1, Y0, H1, NB * 512 / 4, 512 / 4);

    // layer 2: [1024,512] @ W2; split-K=2 (Kc=256) -> 256 blocks
    gemm_split<32, 64, 2, 4, false><<<dim3(256 / 64, NB / 32, 2), 256>>>(
        H1, W2, NB, 256, 512, 256);
    combine_k<2, true, false><<<(NB * 256 / 4 + 255) / 256, 256>>>(
        b2, nullptr, H2, NB * 256 / 4, 256 / 4);

    // layer 3: [1024,256] @ W3; split-K=4 (Kc=64) -> 256 blocks
    gemm_split<32, 64, 2, 4, false><<<dim3(128 / 64, NB / 32, 4), 256>>>(
        H2, W3, NB, 128, 256, 64);
    combine_k<4, false, false><<<(NB * 128 / 4 + 255) / 256, 256>>>(
        b3, nullptr, (float*)d_out, NB * 128 / 4, 128 / 4);
}